// round 16
// baseline (speedup 1.0000x reference)
#include <cuda_runtime.h>
#include <cuda_bf16.h>
#include <cstdint>
#include <math.h>

#define Nn 8192
#define Dd 128
#define NB 64                    // 128-row blocks
#define NT (NB * (NB + 1) / 2)   // 2080 lower-triangle tiles
#define TPC 16                   // tiles per CTA
#define GRID_MAIN (NT / TPC)     // 130

// __device__ globals (allocation-free scratch)
__device__ __nv_bfloat16  g_zb[Nn * Dd];          // normalized rows, bf16
__device__ float          g_acc[NB * NB * 128];   // [K][Q][r] partials, 2MB
__device__ float          g_pos[Nn];
__device__ float          g_partial[32];
__device__ unsigned int   g_arrive[4];            // zero-init (BSS)
__device__ unsigned int   g_release[4];           // monotonic generations

// ---------------------------------------------------------------------------
// helpers (base-sm_103-safe PTX only)
// ---------------------------------------------------------------------------
__device__ __forceinline__ uint32_t smem_u32(const void* p) {
    uint32_t a;
    asm("{ .reg .u64 t; cvta.to.shared.u64 t, %1; cvt.u32.u64 %0, t; }"
        : "=r"(a) : "l"(p));
    return a;
}
__device__ __forceinline__ void cpasync16(uint32_t dst, const void* src) {
    asm volatile("cp.async.cg.shared.global [%0], [%1], 16;"
                 :: "r"(dst), "l"(src) : "memory");
}
__device__ __forceinline__ void ldsm4(uint32_t* r, uint32_t addr) {
    asm volatile("ldmatrix.sync.aligned.m8n8.x4.shared.b16 {%0,%1,%2,%3}, [%4];"
                 : "=r"(r[0]), "=r"(r[1]), "=r"(r[2]), "=r"(r[3]) : "r"(addr));
}
__device__ __forceinline__ void mma16816(float* c, const uint32_t* a,
                                         uint32_t b0, uint32_t b1) {
    asm volatile(
        "mma.sync.aligned.m16n8k16.row.col.f32.bf16.bf16.f32 "
        "{%0,%1,%2,%3}, {%4,%5,%6,%7}, {%8,%9}, {%0,%1,%2,%3};"
        : "+f"(c[0]), "+f"(c[1]), "+f"(c[2]), "+f"(c[3])
        : "r"(a[0]), "r"(a[1]), "r"(a[2]), "r"(a[3]), "r"(b0), "r"(b1));
}
__device__ __forceinline__ unsigned long long pack2(float a, float b) {
    unsigned long long r;
    asm("mov.b64 %0, {%1,%2};" : "=l"(r) : "f"(a), "f"(b));
    return r;
}

// Sense-reversal grid barrier. Safe across graph replays: release[k] is a
// monotonic generation counter; arrive[k] is reset by the last arriver
// before the release increment (kernel boundaries order the next reuse).
__device__ __forceinline__ void grid_barrier(int k) {
    __syncthreads();
    if (threadIdx.x == 0) {
        __threadfence();                                  // publish phase data
        unsigned gen = atomicAdd(&g_release[k], 0u);      // read BEFORE arrive
        if (atomicAdd(&g_arrive[k], 1u) == GRID_MAIN - 1u) {
            g_arrive[k] = 0u;
            __threadfence();
            atomicAdd(&g_release[k], 1u);                 // release
        } else {
            while (atomicAdd(&g_release[k], 0u) == gen) { }
            __threadfence();                              // acquire phase data
        }
    }
    __syncthreads();
}

// ---------------------------------------------------------------------------
// packed exp2 epilogue machinery
// ---------------------------------------------------------------------------
struct EC {
    unsigned long long C1, C0, MG, N1, P5, P4, P3, P2, P1, P0;
};

// rsum += e; csum += e; e = exp(10*x - 10) (2-wide). Optionally mask diag.
template <bool MASKED>
__device__ __forceinline__ void expacc2(float x0, float x1,
                                        unsigned long long& rsum,
                                        unsigned long long& csum,
                                        int R, int C, const EC& c) {
    unsigned long long v2 = pack2(x0, x1);
    unsigned long long t2, zi2, fzi2, f2, p2, r2;
    asm("fma.rn.f32x2 %0, %1, %2, %3;" : "=l"(t2)  : "l"(v2),   "l"(c.C1), "l"(c.C0));
    asm("add.rn.f32x2 %0, %1, %2;"     : "=l"(zi2) : "l"(t2),   "l"(c.MG));
    asm("fma.rn.f32x2 %0, %1, %2, %3;" : "=l"(fzi2): "l"(c.MG), "l"(c.N1), "l"(zi2));
    asm("fma.rn.f32x2 %0, %1, %2, %3;" : "=l"(f2)  : "l"(fzi2), "l"(c.N1), "l"(t2));
    asm("fma.rn.f32x2 %0, %1, %2, %3;" : "=l"(p2)  : "l"(c.P5), "l"(f2),   "l"(c.P4));
    asm("fma.rn.f32x2 %0, %1, %2, %3;" : "=l"(p2)  : "l"(p2),   "l"(f2),   "l"(c.P3));
    asm("fma.rn.f32x2 %0, %1, %2, %3;" : "=l"(p2)  : "l"(p2),   "l"(f2),   "l"(c.P2));
    asm("fma.rn.f32x2 %0, %1, %2, %3;" : "=l"(p2)  : "l"(p2),   "l"(f2),   "l"(c.P1));
    asm("fma.rn.f32x2 %0, %1, %2, %3;" : "=l"(p2)  : "l"(p2),   "l"(f2),   "l"(c.P0));
    uint32_t zlo, zhi, plo, phi;
    asm("mov.b64 {%0,%1}, %2;" : "=r"(zlo), "=r"(zhi) : "l"(zi2));
    asm("mov.b64 {%0,%1}, %2;" : "=r"(plo), "=r"(phi) : "l"(p2));
    uint32_t rlo = plo + (zlo << 23);
    uint32_t rhi = phi + (zhi << 23);
    if (MASKED) {
        if (R == C)     rlo = 0u;
        if (R == C + 1) rhi = 0u;
    }
    asm("mov.b64 %0, {%1,%2};" : "=l"(r2) : "r"(rlo), "r"(rhi));
    asm("add.rn.f32x2 %0, %1, %2;" : "=l"(rsum) : "l"(rsum), "l"(r2));
    asm("add.rn.f32x2 %0, %1, %2;" : "=l"(csum) : "l"(csum), "l"(r2));
}

// 128x128 bf16 tile (row-major) -> swizzled smem (chunk c ^= row&7)
__device__ __forceinline__ void load_tile(uint32_t sbase,
                                          const __nv_bfloat16* src, int tid) {
    #pragma unroll
    for (int p = 0; p < 8; ++p) {
        int idx = p * 256 + tid;
        int r = idx >> 4;
        int c = idx & 15;
        cpasync16(sbase + (uint32_t)(r * 256 + ((c ^ (r & 7)) << 4)),
                  (const void*)(src + r * Dd + c * 8));
    }
}
__device__ __forceinline__ uint32_t tile_addr(uint32_t sbase, int row, int ch) {
    return sbase + (uint32_t)(row * 256 + ((ch ^ (row & 7)) << 4));
}

// ---------------------------------------------------------------------------
// ONE fused persistent kernel: normalize -> GEMM+exp -> gather -> loss
// ---------------------------------------------------------------------------
__global__ void __launch_bounds__(256, 1)
ntxent_all_kernel(const float* __restrict__ x, float* __restrict__ out) {
    extern __shared__ __align__(16) unsigned char dyn[];
    __shared__ float sRow[2][128];
    __shared__ float sCol[2][4][64];
    __shared__ float sred[256];

    const int tid  = threadIdx.x;
    const int w    = tid >> 5;
    const int lane = tid & 31;
    const int wm   = w & 3;
    const int wn   = w >> 2;
    const int bid  = blockIdx.x;
    const uint32_t sbase = smem_u32(dyn);   // 2 stages x (A 32KB + B 32KB)

    // ---------------- Phase 0: normalize rows + exact fp32 pos -------------
    for (int row = bid * 8 + w; row < Nn; row += GRID_MAIN * 8) {
        const int prow = (row + Nn / 2) & (Nn - 1);
        float4 v = reinterpret_cast<const float4*>(x)[row * 32 + lane];
        float4 u = reinterpret_cast<const float4*>(x)[prow * 32 + lane];
        float sv = v.x * v.x + v.y * v.y + v.z * v.z + v.w * v.w;
        float su = u.x * u.x + u.y * u.y + u.z * u.z + u.w * u.w;
        float dd = v.x * u.x + v.y * u.y + v.z * u.z + v.w * u.w;
        #pragma unroll
        for (int o = 16; o; o >>= 1) {
            sv += __shfl_xor_sync(0xffffffffu, sv, o);
            su += __shfl_xor_sync(0xffffffffu, su, o);
            dd += __shfl_xor_sync(0xffffffffu, dd, o);
        }
        const float nv = fmaxf(sqrtf(sv), 1e-8f);
        const float nu = fmaxf(sqrtf(su), 1e-8f);
        const float inv = 1.0f / nv;
        __nv_bfloat162 b0 = __floats2bfloat162_rn(v.x * inv, v.y * inv);
        __nv_bfloat162 b1 = __floats2bfloat162_rn(v.z * inv, v.w * inv);
        uint2 wv;
        wv.x = *reinterpret_cast<uint32_t*>(&b0);
        wv.y = *reinterpret_cast<uint32_t*>(&b1);
        reinterpret_cast<uint2*>(g_zb)[row * 32 + lane] = wv;
        if (lane == 0) g_pos[row] = 10.0f * dd / (nv * nu);
    }
    grid_barrier(0);

    // ---------------- Phase 1: symmetric tile GEMM + exp -------------------
    // decode first tile id -> (I, J), J <= I
    int t0 = bid * TPC;
    int I = 0, base = 0;
    while (base + I + 1 <= t0) { base += I + 1; ++I; }
    int J = t0 - base;

    load_tile(sbase, g_zb + (size_t)I * 128 * Dd, tid);
    load_tile(sbase + 32768u, g_zb + (size_t)J * 128 * Dd, tid);
    asm volatile("cp.async.commit_group;" ::: "memory");

    EC c;
    const float L = 14.4269504088896341f;
    c.C1 = pack2(L, L);   c.C0 = pack2(-L, -L);
    c.MG = pack2(12582912.0f, 12582912.0f);
    c.N1 = pack2(-1.0f, -1.0f);
    c.P5 = pack2(1.33335581e-3f, 1.33335581e-3f);
    c.P4 = pack2(9.61812911e-3f, 9.61812911e-3f);
    c.P3 = pack2(5.55041087e-2f, 5.55041087e-2f);
    c.P2 = pack2(2.40226507e-1f, 2.40226507e-1f);
    c.P1 = pack2(6.93147181e-1f, 6.93147181e-1f);
    c.P0 = pack2(1.0f, 1.0f);

    int Icur = I, Jcur = J;
    for (int i = 0; i < TPC; ++i) {
        int In = Icur, Jn = Jcur + 1;
        if (Jn > In) { ++In; Jn = 0; }
        if (i + 1 < TPC) {
            uint32_t sb = sbase + (uint32_t)(((i + 1) & 1) * 65536);
            load_tile(sb, g_zb + (size_t)In * 128 * Dd, tid);
            load_tile(sb + 32768u, g_zb + (size_t)Jn * 128 * Dd, tid);
            asm volatile("cp.async.commit_group;" ::: "memory");
            asm volatile("cp.async.wait_group 1;" ::: "memory");
        } else {
            asm volatile("cp.async.wait_group 0;" ::: "memory");
        }
        __syncthreads();   // tile i visible; sRow/sCol of tile i-1 consumed

        const uint32_t sA = sbase + (uint32_t)((i & 1) * 65536);
        const uint32_t sB = sA + 32768u;

        uint32_t Af[2][8][4];
        #pragma unroll
        for (int mf = 0; mf < 2; ++mf) {
            const int arow = wm * 32 + mf * 16 + (lane & 15);
            #pragma unroll
            for (int k = 0; k < 8; ++k)
                ldsm4(Af[mf][k], tile_addr(sA, arow, 2 * k + (lane >> 4)));
        }

        unsigned long long rsv[2][2], ct[4][2];
        #pragma unroll
        for (int a = 0; a < 2; ++a) { rsv[a][0] = 0ull; rsv[a][1] = 0ull; }
        #pragma unroll
        for (int a = 0; a < 4; ++a) { ct[a][0] = 0ull; ct[a][1] = 0ull; }

        const bool diagT = (Icur == Jcur);
        const int Rl = lane >> 2;
        const int Cl = (lane & 3) * 2;

        #pragma unroll
        for (int p = 0; p < 4; ++p) {
            float acc[2][2][4];
            #pragma unroll
            for (int a = 0; a < 2; ++a)
                #pragma unroll
                for (int b = 0; b < 2; ++b)
                    acc[a][b][0] = acc[a][b][1] = acc[a][b][2] = acc[a][b][3] = 0.0f;

            const int brow = wn * 64 + p * 16 + (lane & 15);
            #pragma unroll
            for (int k = 0; k < 8; ++k) {
                uint32_t b[4];
                ldsm4(b, tile_addr(sB, brow, 2 * k + (lane >> 4)));
                mma16816(acc[0][0], Af[0][k], b[0], b[2]);
                mma16816(acc[0][1], Af[0][k], b[1], b[3]);
                mma16816(acc[1][0], Af[1][k], b[0], b[2]);
                mma16816(acc[1][1], Af[1][k], b[1], b[3]);
            }

            #pragma unroll
            for (int mf = 0; mf < 2; ++mf) {
                #pragma unroll
                for (int nh = 0; nh < 2; ++nh) {
                    const float* a = acc[mf][nh];
                    if (diagT) {
                        const int R0 = wm * 32 + mf * 16 + Rl;
                        const int C0 = wn * 64 + p * 16 + nh * 8 + Cl;
                        expacc2<true >(a[0], a[1], rsv[mf][0], ct[p][nh], R0,     C0, c);
                        expacc2<true >(a[2], a[3], rsv[mf][1], ct[p][nh], R0 + 8, C0, c);
                    } else {
                        expacc2<false>(a[0], a[1], rsv[mf][0], ct[p][nh], 0, 0, c);
                        expacc2<false>(a[2], a[3], rsv[mf][1], ct[p][nh], 0, 0, c);
                    }
                }
            }
        }

        // ---- row sums: reduce over lane&3, combine wn halves via smem ----
        #pragma unroll
        for (int mf = 0; mf < 2; ++mf) {
            #pragma unroll
            for (int h = 0; h < 2; ++h) {
                float lo, hi;
                asm("mov.b64 {%0,%1}, %2;" : "=f"(lo), "=f"(hi) : "l"(rsv[mf][h]));
                float s = lo + hi;
                s += __shfl_xor_sync(0xffffffffu, s, 1);
                s += __shfl_xor_sync(0xffffffffu, s, 2);
                if ((lane & 3) == 0)
                    sRow[wn][wm * 32 + mf * 16 + h * 8 + Rl] = s;
            }
        }
        // ---- col sums: reduce over rows (lane>>2), stash per (wn, wm) ----
        #pragma unroll
        for (int p = 0; p < 4; ++p) {
            #pragma unroll
            for (int nh = 0; nh < 2; ++nh) {
                float lo, hi;
                asm("mov.b64 {%0,%1}, %2;" : "=f"(lo), "=f"(hi) : "l"(ct[p][nh]));
                #pragma unroll
                for (int o = 4; o <= 16; o <<= 1) {
                    lo += __shfl_xor_sync(0xffffffffu, lo, o);
                    hi += __shfl_xor_sync(0xffffffffu, hi, o);
                }
                if (lane < 4) {
                    sCol[wn][wm][p * 16 + nh * 8 + lane * 2]     = lo;
                    sCol[wn][wm][p * 16 + nh * 8 + lane * 2 + 1] = hi;
                }
            }
        }
        __syncthreads();

        if (tid < 128) {
            g_acc[((size_t)Icur * NB + Jcur) * 128 + tid] =
                sRow[0][tid] + sRow[1][tid];
        } else if (!diagT) {
            const int cx = tid - 128;
            const float v = sCol[cx >> 6][0][cx & 63] + sCol[cx >> 6][1][cx & 63]
                          + sCol[cx >> 6][2][cx & 63] + sCol[cx >> 6][3][cx & 63];
            g_acc[((size_t)Jcur * NB + Icur) * 128 + cx] = v;
        }
        Icur = In; Jcur = Jn;
    }
    grid_barrier(1);

    // ---------------- Phase 2: gather + per-row loss + block reduce --------
    if (bid < 32) {
        const int row = bid * 256 + tid;
        const int K = row >> 7, rl = row & 127;
        const float* pa = g_acc + ((size_t)K * NB) * 128 + rl;
        float s = 0.0f;
        #pragma unroll
        for (int Q = 0; Q < NB; ++Q) s += pa[(size_t)Q * 128];
        sred[tid] = 10.0f + logf(s) - g_pos[row];
        __syncthreads();
        #pragma unroll
        for (int o = 128; o; o >>= 1) {
            if (tid < o) sred[tid] += sred[tid + o];
            __syncthreads();
        }
        if (tid == 0) g_partial[bid] = sred[0];
    }
    grid_barrier(2);

    // ---------------- Phase 3: final scalar ------------------------------
    if (bid == 0 && w == 0) {
        float v = g_partial[lane];
        #pragma unroll
        for (int o = 16; o; o >>= 1) v += __shfl_xor_sync(0xffffffffu, v, o);
        if (lane == 0) out[0] = v * (1.0f / (float)Nn);
    }
}

// ---------------------------------------------------------------------------
extern "C" void kernel_launch(void* const* d_in, const int* in_sizes, int n_in,
                              void* d_out, int out_size) {
    const float* x = (const float*)d_in[0];
    float* out = (float*)d_out;
    (void)in_sizes; (void)n_in; (void)out_size;

    const int dyn = 2 * 65536;   // 2 stages x (A + B)
    cudaFuncSetAttribute(ntxent_all_kernel,
                         cudaFuncAttributeMaxDynamicSharedMemorySize, dyn);

    ntxent_all_kernel<<<GRID_MAIN, 256, dyn>>>(x, out);
}